// round 9
// baseline (speedup 1.0000x reference)
#include <cuda_runtime.h>
#include <cstdint>

#define BATCH 2048
#define NH    512
#define HC    256
#define ROWS  16
#define NSL   4            // k-slices
#define KSL   (NH / NSL)   // 128 k per slice
#define TOPT  8
#define IDXCAP 64
#define GRID  296
#define NQ    (HC + BATCH / TOPT)   // 256 bottom + 256 top

// smem byte offsets
#define OFF_IN   0                       // s_in2: ROWS*NH u64 = 65536 B
#define OFF_LA   (ROWS * NH * 8)         // s_logA: ROWS*HC f32 = 16384 B
#define OFF_LB   (OFF_LA + ROWS * HC * 4)
#define OFF_IDX  (OFF_LB + ROWS * HC * 4)
#define OFF_CNT  (OFF_IDX + IDXCAP * 4)
#define OFF_POP  (OFF_CNT + 4)
#define SMEM_BYTES (OFF_POP + 12)        // ~98.6 KB -> 2 CTAs/SM

__device__ float g_top_prob[BATCH];
__device__ float g_bot_prob[BATCH];
__device__ int   g_queue;
__device__ int   g_done;

// ---------------- PTX helpers ----------------
__device__ __forceinline__ uint64_t pack2(float lo, float hi) {
    uint64_t d; asm("mov.b64 %0, {%1,%2};" : "=l"(d) : "f"(lo), "f"(hi)); return d;
}
__device__ __forceinline__ uint64_t fma2(uint64_t a, uint64_t b, uint64_t c) {
    uint64_t d; asm("fma.rn.f32x2 %0, %1, %2, %3;" : "=l"(d) : "l"(a), "l"(b), "l"(c)); return d;
}
__device__ __forceinline__ uint64_t add2(uint64_t a, uint64_t b) {
    uint64_t d; asm("add.rn.f32x2 %0, %1, %2;" : "=l"(d) : "l"(a), "l"(b)); return d;
}
__device__ __forceinline__ uint64_t ldg64nc(const float* p) {
    uint64_t v; asm volatile("ld.global.nc.b64 %0, [%1];" : "=l"(v) : "l"(p)); return v;
}
__device__ __forceinline__ void lds128(uint64_t& a, uint64_t& b, uint32_t addr) {
    asm volatile("ld.shared.v2.u64 {%0,%1}, [%2];" : "=l"(a), "=l"(b) : "r"(addr));
}
__device__ __forceinline__ uint64_t lds64(uint32_t addr) {
    uint64_t v; asm volatile("ld.shared.b64 %0, [%1];" : "=l"(v) : "r"(addr)); return v;
}
__device__ __forceinline__ void sts64(uint32_t addr, uint64_t v) {
    asm volatile("st.shared.b64 [%0], %1;" :: "r"(addr), "l"(v));
}
__device__ __forceinline__ void sts128(uint32_t addr, uint64_t a, uint64_t b) {
    asm volatile("st.shared.v2.u64 [%0], {%1,%2};" :: "r"(addr), "l"(a), "l"(b));
}

// ---------------------------------------------------------------------------
// Per-slice GEMM: SA rows x col-pair {2g,2g+1}, k in [q*KSL, (q+1)*KSL).
// W via LDG.64 u64 (adjacent cols), depth-8 register ring prefetch.
// x via broadcast LDS.128 of duplicated pairs. Zero pack instructions.
// Slice partials combined in two smem buffers (A: q3 then q1; B: q2 then q0+bias).
// ---------------------------------------------------------------------------
template <int SA>
__device__ __forceinline__ void gemm_slice(
    uint32_t x_base,           // smem addr of s_in2[0][q*KSL]
    uint32_t logA, uint32_t logB,  // smem addrs of s_logA/B [0][2g]
    const float* __restrict__ wp,  // W + (q*KSL)*HC + 2g
    int q, uint64_t bias2)
{
    uint64_t acc[SA];
#pragma unroll
    for (int s = 0; s < SA; s++) acc[s] = 0ull;

    uint64_t wbuf[8];
#pragma unroll
    for (int i = 0; i < 8; i++) wbuf[i] = ldg64nc(wp + (size_t)i * HC);
    const float* wn = wp + (size_t)8 * HC;

    // main blocks with prefetch
    for (int kb = 0; kb < KSL - 8; kb += 8) {
#pragma unroll
        for (int i = 0; i < 8; i += 2) {
            uint64_t w0 = wbuf[i], w1 = wbuf[i + 1];
            wbuf[i]     = ldg64nc(wn + (size_t)i * HC);
            wbuf[i + 1] = ldg64nc(wn + (size_t)(i + 1) * HC);
            uint32_t xa = x_base + (uint32_t)(kb + i) * 8;
#pragma unroll
            for (int s = 0; s < SA; s++) {
                uint64_t x0, x1;
                lds128(x0, x1, xa + (uint32_t)s * (NH * 8));
                acc[s] = fma2(w0, x0, acc[s]);
                acc[s] = fma2(w1, x1, acc[s]);
            }
        }
        wn += (size_t)8 * HC;
    }
    // last block, no prefetch
    {
        const int kb = KSL - 8;
#pragma unroll
        for (int i = 0; i < 8; i += 2) {
            uint64_t w0 = wbuf[i], w1 = wbuf[i + 1];
            uint32_t xa = x_base + (uint32_t)(kb + i) * 8;
#pragma unroll
            for (int s = 0; s < SA; s++) {
                uint64_t x0, x1;
                lds128(x0, x1, xa + (uint32_t)s * (NH * 8));
                acc[s] = fma2(w0, x0, acc[s]);
                acc[s] = fma2(w1, x1, acc[s]);
            }
        }
    }

    // combine slices: q3 writes A, q2 writes B; sync; q1 adds into A,
    // q0 adds (acc + bias) into B; sync. softmax reads A+B.
    if (q == 3) {
#pragma unroll
        for (int s = 0; s < SA; s++) sts64(logA + (uint32_t)s * (HC * 4), acc[s]);
    } else if (q == 2) {
#pragma unroll
        for (int s = 0; s < SA; s++) sts64(logB + (uint32_t)s * (HC * 4), acc[s]);
    }
    __syncthreads();
    if (q == 1) {
#pragma unroll
        for (int s = 0; s < SA; s++) {
            uint32_t a = logA + (uint32_t)s * (HC * 4);
            sts64(a, add2(acc[s], lds64(a)));
        }
    } else if (q == 0) {
#pragma unroll
        for (int s = 0; s < SA; s++) {
            uint32_t a = logB + (uint32_t)s * (HC * 4);
            sts64(a, add2(add2(acc[s], bias2), lds64(a)));
        }
    }
    __syncthreads();
}

// softmax over A[r][c]+B[r][c]
__device__ __forceinline__ void softmax_row2(
    const float* A, const float* B, int lane, float& m_out, float& sum_out)
{
    float m = -1e30f;
#pragma unroll
    for (int cc = lane; cc < HC; cc += 32) m = fmaxf(m, A[cc] + B[cc]);
#pragma unroll
    for (int o = 16; o > 0; o >>= 1) m = fmaxf(m, __shfl_xor_sync(0xffffffffu, m, o));
    float sum = 0.f;
#pragma unroll
    for (int cc = lane; cc < HC; cc += 32) sum += __expf(A[cc] + B[cc] - m);
#pragma unroll
    for (int o = 16; o > 0; o >>= 1) sum += __shfl_xor_sync(0xffffffffu, sum, o);
    m_out = m; sum_out = sum;
}

// duplicated gather: S rows of inputs into s_in2 as (x,x) u64 pairs
__device__ __forceinline__ void gather_dup(
    uint32_t sb, const float* __restrict__ inputs,
    const int* rowmap, int S, int tid)   // rowmap: smem idx list or nullptr
{
    for (int idx = tid; idx < S * (NH / 4); idx += 512) {
        int s = idx >> 7;
        int k4 = (idx & 127) << 2;
        int b = rowmap[s];
        float4 v = ((const float4*)(inputs + (size_t)b * NH))[idx & 127];
        uint32_t a = sb + (uint32_t)(s * NH + k4) * 8;
        sts128(a, pack2(v.x, v.x), pack2(v.y, v.y));
        sts128(a + 16, pack2(v.z, v.z), pack2(v.w, v.w));
    }
}

// ---------------------------------------------------------------------------
__global__ __launch_bounds__(512, 2) void fused_kernel(
    const float* __restrict__ inputs, const int* __restrict__ labels,
    const int* __restrict__ parent,
    const float* __restrict__ topW, const float* __restrict__ topB,
    const float* __restrict__ botW, const float* __restrict__ botB,
    float* __restrict__ out)
{
    extern __shared__ char sm[];
    uint32_t sb = (uint32_t)__cvta_generic_to_shared(sm);
    float* s_logA = (float*)(sm + OFF_LA);
    float* s_logB = (float*)(sm + OFF_LB);
    int* s_idx = (int*)(sm + OFF_IDX);
    int* s_cnt = (int*)(sm + OFF_CNT);
    int* s_pop = (int*)(sm + OFF_POP);

    int tid = threadIdx.x;
    int q = tid >> 7;            // k-slice
    int g = tid & 127;           // column pair {2g, 2g+1}
    int wid = tid >> 5, lane = tid & 31;

    uint32_t x_base = sb + OFF_IN + (uint32_t)(q * KSL) * 8;
    uint32_t logA = sb + OFF_LA + (uint32_t)g * 8;
    uint32_t logB = sb + OFF_LB + (uint32_t)g * 8;

    for (;;) {
        __syncthreads();
        if (tid == 0) *s_pop = atomicAdd(&g_queue, 1);
        __syncthreads();
        int item = *s_pop;
        if (item >= NQ) break;

        if (item >= HC) {
            // ----------------- TOP tile (8 samples) -----------------
            int b0 = (item - HC) * TOPT;
            if (tid < TOPT) s_idx[tid] = b0 + tid;   // rowmap
            __syncthreads();
            gather_dup(sb + OFF_IN, inputs, s_idx, TOPT, tid);
            __syncthreads();

            uint64_t bias2 = ldg64nc(topB + 2 * g);
            gemm_slice<TOPT>(x_base, logA, logB,
                             topW + (size_t)(q * KSL) * HC + 2 * g, q, bias2);

            if (wid < TOPT) {
                const float* A = s_logA + wid * HC;
                const float* B = s_logB + wid * HC;
                float m, sum;
                softmax_row2(A, B, lane, m, sum);
                if (lane == 0) {
                    int b = b0 + wid;
                    int p = parent[b];
                    g_top_prob[b] = __expf(A[p] + B[p] - m) / sum;
                }
            }
        } else {
            // ----------------- BOTTOM parent -----------------
            int p = item;
            if (tid == 0) *s_cnt = 0;
            __syncthreads();
            for (int i = tid; i < BATCH; i += 512) {
                if (parent[i] == p) {
                    int qq = atomicAdd(s_cnt, 1);
                    if (qq < IDXCAP) s_idx[qq] = i;
                }
            }
            __syncthreads();
            int n = min(*s_cnt, IDXCAP);
            if (n == 0) continue;

            const float* wp = botW + (size_t)p * NH * HC + (size_t)(q * KSL) * HC + 2 * g;
            uint64_t bias2 = ldg64nc(botB + (size_t)p * HC + 2 * g);

            for (int c0 = 0; c0 < n; c0 += ROWS) {
                int S = min(ROWS, n - c0);
                __syncthreads();             // prev softmax done with logs
                gather_dup(sb + OFF_IN, inputs, s_idx + c0, S, tid);
                __syncthreads();

                if (S <= 8) gemm_slice<8>(x_base, logA, logB, wp, q, bias2);
                else        gemm_slice<16>(x_base, logA, logB, wp, q, bias2);

                if (wid < S) {
                    const float* A = s_logA + wid * HC;
                    const float* B = s_logB + wid * HC;
                    float m, sum;
                    softmax_row2(A, B, lane, m, sum);
                    if (lane == 0) {
                        int b = s_idx[c0 + wid];
                        int l = labels[b];
                        g_bot_prob[b] = __expf(A[l] + B[l] - m) / sum;
                    }
                }
            }
        }
    }

    // ----------------- last-CTA finalize -----------------
    __syncthreads();
    __threadfence();
    if (tid == 0) *s_pop = atomicAdd(&g_done, 1);
    __syncthreads();
    if (*s_pop == GRID - 1) {
        __threadfence();
#pragma unroll
        for (int i = 0; i < BATCH / 512; i++) {
            int b = tid + i * 512;
            out[b] = g_top_prob[b] * g_bot_prob[b];
        }
        __threadfence();
        if (tid == 0) { g_done = 0; g_queue = 0; }
    }
}

// ---------------------------------------------------------------------------
extern "C" void kernel_launch(void* const* d_in, const int* in_sizes, int n_in,
                              void* d_out, int out_size) {
    const float* inputs = (const float*)d_in[0];
    const int*   labels = (const int*)d_in[1];
    const int*   parent = (const int*)d_in[2];
    const float* topW   = (const float*)d_in[3];
    const float* topB   = (const float*)d_in[4];
    const float* botW   = (const float*)d_in[5];
    const float* botB   = (const float*)d_in[6];
    float* out = (float*)d_out;

    cudaFuncSetAttribute(fused_kernel,
                         cudaFuncAttributeMaxDynamicSharedMemorySize, SMEM_BYTES);

    fused_kernel<<<GRID, 512, SMEM_BYTES>>>(inputs, labels, parent,
                                            topW, topB, botW, botB, out);
}

// round 11
// speedup vs baseline: 1.2200x; 1.2200x over previous
#include <cuda_runtime.h>
#include <cstdint>

#define BATCH 2048
#define NH    512
#define HC    256
#define ROWS  8
#define NSL   4
#define KSL   (NH / NSL)   // 128
#define TOPT  8
#define IDXCAP 64
#define GRID  592          // 148 SMs * 4 CTAs
#define NQ    (HC + BATCH / TOPT)   // 256 bottom + 256 top

// smem byte offsets
#define OFF_IN   0                         // dup-x: ROWS*NH u64 = 32768 B
#define OFF_LA   32768                     // logA: ROWS*HC f32 = 8192 B
#define OFF_LB   (OFF_LA + ROWS * HC * 4)  // logB: 8192 B
#define OFF_IDX  (OFF_LB + ROWS * HC * 4)
#define OFF_CNT  (OFF_IDX + IDXCAP * 4)
#define OFF_POP  (OFF_CNT + 4)
#define SMEM_BYTES (OFF_POP + 12)          // 49424 B -> 4 CTAs/SM

__device__ float g_top_prob[BATCH];
__device__ float g_bot_prob[BATCH];
__device__ int   g_queue;
__device__ int   g_done;

// ---------------- PTX helpers ----------------
__device__ __forceinline__ uint64_t pack2(float lo, float hi) {
    uint64_t d; asm("mov.b64 %0, {%1,%2};" : "=l"(d) : "f"(lo), "f"(hi)); return d;
}
__device__ __forceinline__ uint64_t fma2(uint64_t a, uint64_t b, uint64_t c) {
    uint64_t d; asm("fma.rn.f32x2 %0, %1, %2, %3;" : "=l"(d) : "l"(a), "l"(b), "l"(c)); return d;
}
__device__ __forceinline__ uint64_t add2(uint64_t a, uint64_t b) {
    uint64_t d; asm("add.rn.f32x2 %0, %1, %2;" : "=l"(d) : "l"(a), "l"(b)); return d;
}
__device__ __forceinline__ void ldg128nc(uint64_t& a, uint64_t& b, const float* p) {
    asm volatile("ld.global.nc.v2.u64 {%0,%1}, [%2];" : "=l"(a), "=l"(b) : "l"(p));
}
__device__ __forceinline__ void lds128(uint64_t& a, uint64_t& b, uint32_t addr) {
    asm volatile("ld.shared.v2.u64 {%0,%1}, [%2];" : "=l"(a), "=l"(b) : "r"(addr));
}
__device__ __forceinline__ void sts128(uint32_t addr, uint64_t a, uint64_t b) {
    asm volatile("st.shared.v2.u64 [%0], {%1,%2};" :: "r"(addr), "l"(a), "l"(b));
}

// ---------------------------------------------------------------------------
// 4-column GEMM slice: SA rows x cols {4g..4g+3}, k in [q*KSL, (q+1)*KSL).
// W: LDG.128 (2 u64 col-pairs per k-row), ping-pong ring.
//   Sub-block A handles 2k-step st (consumed again at st+2 -> prefetch st+2),
//   sub-block B handles st+1 (prefetch st+3).   [R10 bug was st+4/st+5]
// x: broadcast LDS.128 of duplicated pairs -> 4 fma2 per LDS, zero packs.
// Partials combined in two smem buffers (q3->A, q2->B; sync; q1+=A, q0+=B+bias).
// ---------------------------------------------------------------------------
template <int SA>
__device__ __forceinline__ void gemm4(
    uint32_t xb,                   // smem addr of dup-x[0][q*KSL]
    uint32_t la, uint32_t lb,      // smem addrs of logA/B [0][4g]
    const float* __restrict__ wp,  // W + (q*KSL)*HC + 4g
    int q, uint64_t bL, uint64_t bH)
{
    uint64_t accL[SA], accH[SA];
#pragma unroll
    for (int s = 0; s < SA; s++) { accL[s] = 0ull; accH[s] = 0ull; }

    const int NST = KSL / 2;       // 64 2k-steps
    uint64_t A[4], B[4];
    ldg128nc(A[0], A[1], wp);              // k-rows 0,1 (step 0)
    ldg128nc(A[2], A[3], wp + HC);
    ldg128nc(B[0], B[1], wp + 2 * HC);     // k-rows 2,3 (step 1)
    ldg128nc(B[2], B[3], wp + 3 * HC);

    for (int st = 0; st < NST; st += 2) {
        {   // step st (buffer A: k = 2st, 2st+1), prefetch A <- step st+2
            uint64_t w0 = A[0], w1 = A[1], w2 = A[2], w3 = A[3];
            int ip = (st + 2 < NST) ? (st + 2) : st;
            const float* wn = wp + (size_t)(2 * ip) * HC;
            ldg128nc(A[0], A[1], wn);
            ldg128nc(A[2], A[3], wn + HC);
            uint32_t xa = xb + (uint32_t)(2 * st) * 8;
#pragma unroll
            for (int s = 0; s < SA; s++) {
                uint64_t x0, x1;
                lds128(x0, x1, xa);
                accL[s] = fma2(w0, x0, accL[s]);
                accH[s] = fma2(w1, x0, accH[s]);
                accL[s] = fma2(w2, x1, accL[s]);
                accH[s] = fma2(w3, x1, accH[s]);
                xa += NH * 8;
            }
        }
        {   // step st+1 (buffer B: k = 2st+2, 2st+3), prefetch B <- step st+3
            uint64_t w0 = B[0], w1 = B[1], w2 = B[2], w3 = B[3];
            int ip = (st + 3 < NST) ? (st + 3) : (st + 1);
            const float* wn = wp + (size_t)(2 * ip) * HC;
            ldg128nc(B[0], B[1], wn);
            ldg128nc(B[2], B[3], wn + HC);
            uint32_t xa = xb + (uint32_t)(2 * st + 2) * 8;
#pragma unroll
            for (int s = 0; s < SA; s++) {
                uint64_t x0, x1;
                lds128(x0, x1, xa);
                accL[s] = fma2(w0, x0, accL[s]);
                accH[s] = fma2(w1, x0, accH[s]);
                accL[s] = fma2(w2, x1, accL[s]);
                accH[s] = fma2(w3, x1, accH[s]);
                xa += NH * 8;
            }
        }
    }

    // combine slices
    if (q == 3) {
#pragma unroll
        for (int s = 0; s < SA; s++) sts128(la + (uint32_t)s * (HC * 4), accL[s], accH[s]);
    } else if (q == 2) {
#pragma unroll
        for (int s = 0; s < SA; s++) sts128(lb + (uint32_t)s * (HC * 4), accL[s], accH[s]);
    }
    __syncthreads();
    if (q == 1) {
#pragma unroll
        for (int s = 0; s < SA; s++) {
            uint32_t a = la + (uint32_t)s * (HC * 4);
            uint64_t p0, p1;
            lds128(p0, p1, a);
            sts128(a, add2(accL[s], p0), add2(accH[s], p1));
        }
    } else if (q == 0) {
#pragma unroll
        for (int s = 0; s < SA; s++) {
            uint32_t a = lb + (uint32_t)s * (HC * 4);
            uint64_t p0, p1;
            lds128(p0, p1, a);
            sts128(a, add2(add2(accL[s], bL), p0), add2(add2(accH[s], bH), p1));
        }
    }
    __syncthreads();
}

// softmax over A[c]+B[c]
__device__ __forceinline__ void softmax_row2(
    const float* A, const float* B, int lane, float& m_out, float& sum_out)
{
    float m = -1e30f;
#pragma unroll
    for (int cc = lane; cc < HC; cc += 32) m = fmaxf(m, A[cc] + B[cc]);
#pragma unroll
    for (int o = 16; o > 0; o >>= 1) m = fmaxf(m, __shfl_xor_sync(0xffffffffu, m, o));
    float sum = 0.f;
#pragma unroll
    for (int cc = lane; cc < HC; cc += 32) sum += __expf(A[cc] + B[cc] - m);
#pragma unroll
    for (int o = 16; o > 0; o >>= 1) sum += __shfl_xor_sync(0xffffffffu, sum, o);
    m_out = m; sum_out = sum;
}

// gather S rows into dup-x smem as (x,x) u64 pairs
__device__ __forceinline__ void gather_dup(
    uint32_t xin, const float* __restrict__ inputs,
    const int* rowmap, int S, int tid)
{
    for (int idx = tid; idx < S * (NH / 4); idx += 256) {
        int s = idx >> 7;
        int k4 = (idx & 127) << 2;
        int b = rowmap[s];
        float4 v = ((const float4*)(inputs + (size_t)b * NH))[idx & 127];
        uint32_t a = xin + (uint32_t)(s * NH + k4) * 8;
        sts128(a, pack2(v.x, v.x), pack2(v.y, v.y));
        sts128(a + 16, pack2(v.z, v.z), pack2(v.w, v.w));
    }
}

// ---------------------------------------------------------------------------
__global__ __launch_bounds__(256, 4) void fused_kernel(
    const float* __restrict__ inputs, const int* __restrict__ labels,
    const int* __restrict__ parent,
    const float* __restrict__ topW, const float* __restrict__ topB,
    const float* __restrict__ botW, const float* __restrict__ botB,
    float* __restrict__ out)
{
    extern __shared__ char sm[];
    uint32_t sb = (uint32_t)__cvta_generic_to_shared(sm);
    float* s_logA = (float*)(sm + OFF_LA);
    float* s_logB = (float*)(sm + OFF_LB);
    int* s_idx = (int*)(sm + OFF_IDX);
    int* s_cnt = (int*)(sm + OFF_CNT);
    int* s_pop = (int*)(sm + OFF_POP);

    int tid = threadIdx.x;
    int q = tid >> 6;            // k-slice 0..3
    int g = tid & 63;            // columns 4g..4g+3
    int wid = tid >> 5, lane = tid & 31;

    uint32_t xin = sb + OFF_IN;
    uint32_t xb = xin + (uint32_t)(q * KSL) * 8;
    uint32_t la = sb + OFF_LA + (uint32_t)g * 16;
    uint32_t lb = sb + OFF_LB + (uint32_t)g * 16;

    for (;;) {
        __syncthreads();
        if (tid == 0) *s_pop = atomicAdd(&g_queue, 1);
        __syncthreads();
        int item = *s_pop;
        if (item >= NQ) break;

        if (item >= HC) {
            // ----------------- TOP tile (8 samples) -----------------
            int b0 = (item - HC) * TOPT;
            if (tid < TOPT) s_idx[tid] = b0 + tid;
            __syncthreads();
            gather_dup(xin, inputs, s_idx, TOPT, tid);
            __syncthreads();

            uint64_t bL, bH;
            ldg128nc(bL, bH, topB + 4 * g);
            gemm4<TOPT>(xb, la, lb, topW + (size_t)(q * KSL) * HC + 4 * g, q, bL, bH);

            const float* A = s_logA + wid * HC;
            const float* B = s_logB + wid * HC;
            float m, sum;
            softmax_row2(A, B, lane, m, sum);
            if (lane == 0) {
                int b = b0 + wid;
                int p = parent[b];
                g_top_prob[b] = __expf(A[p] + B[p] - m) / sum;
            }
        } else {
            // ----------------- BOTTOM parent -----------------
            int p = item;
            if (tid == 0) *s_cnt = 0;
            __syncthreads();
            for (int i = tid; i < BATCH; i += 256) {
                if (parent[i] == p) {
                    int qq = atomicAdd(s_cnt, 1);
                    if (qq < IDXCAP) s_idx[qq] = i;
                }
            }
            __syncthreads();
            int n = min(*s_cnt, IDXCAP);
            if (n == 0) continue;

            const float* wp = botW + (size_t)p * NH * HC + (size_t)(q * KSL) * HC + 4 * g;
            uint64_t bL, bH;
            ldg128nc(bL, bH, botB + (size_t)p * HC + 4 * g);

            for (int c0 = 0; c0 < n; c0 += ROWS) {
                int S = min(ROWS, n - c0);
                __syncthreads();
                gather_dup(xin, inputs, s_idx + c0, S, tid);
                __syncthreads();

                if (S <= 4) gemm4<4>(xb, la, lb, wp, q, bL, bH);
                else        gemm4<8>(xb, la, lb, wp, q, bL, bH);

                if (wid < S) {
                    const float* A = s_logA + wid * HC;
                    const float* B = s_logB + wid * HC;
                    float m, sum;
                    softmax_row2(A, B, lane, m, sum);
                    if (lane == 0) {
                        int b = s_idx[c0 + wid];
                        int l = labels[b];
                        g_bot_prob[b] = __expf(A[l] + B[l] - m) / sum;
                    }
                }
            }
        }
    }

    // ----------------- last-CTA finalize -----------------
    __syncthreads();
    __threadfence();
    if (tid == 0) *s_pop = atomicAdd(&g_done, 1);
    __syncthreads();
    if (*s_pop == GRID - 1) {
        __threadfence();
#pragma unroll
        for (int i = 0; i < BATCH / 256; i++) {
            int b = tid + i * 256;
            out[b] = g_top_prob[b] * g_bot_prob[b];
        }
        __threadfence();
        if (tid == 0) { g_done = 0; g_queue = 0; }
    }
}

// ---------------------------------------------------------------------------
extern "C" void kernel_launch(void* const* d_in, const int* in_sizes, int n_in,
                              void* d_out, int out_size) {
    const float* inputs = (const float*)d_in[0];
    const int*   labels = (const int*)d_in[1];
    const int*   parent = (const int*)d_in[2];
    const float* topW   = (const float*)d_in[3];
    const float* topB   = (const float*)d_in[4];
    const float* botW   = (const float*)d_in[5];
    const float* botB   = (const float*)d_in[6];
    float* out = (float*)d_out;

    cudaFuncSetAttribute(fused_kernel,
                         cudaFuncAttributeMaxDynamicSharedMemorySize, SMEM_BYTES);

    fused_kernel<<<GRID, 256, SMEM_BYTES>>>(inputs, labels, parent,
                                            topW, topB, botW, botB, out);
}

// round 12
// speedup vs baseline: 1.4932x; 1.2239x over previous
#include <cuda_runtime.h>
#include <cstdint>

#define BATCH 2048
#define NH    512
#define HC    256
#define TILE  16
#define TOPT  16           // samples per top tile
#define IDXCAP 128

#define GRID  296          // 148 SMs * 2 CTAs, one wave
#define NQ    (HC + BATCH / TOPT)   // 256 bottom + 128 top = 384 items

// dynamic smem layout (floats)
#define S_LOG  (TILE * NH)            // s_in: [0, 8192)
#define S_IDX  (S_LOG + TILE * HC)    // s_log: [8192, 12288)
#define S_CNT  (S_IDX + IDXCAP)
#define S_POP  (S_CNT + 1)
#define SMEM_FLOATS (S_POP + 3)
#define SMEM_BYTES  (SMEM_FLOATS * 4) // ~49.7 KB -> 2 CTAs/SM

__device__ float g_top_prob[BATCH];
__device__ float g_bot_prob[BATCH];
__device__ int   g_queue;   // work queue cursor (self-resetting)
__device__ int   g_done;    // CTA completion counter (self-resetting)

// ---------------- packed f32x2 helpers ----------------
__device__ __forceinline__ uint64_t pack2(float lo, float hi) {
    uint64_t d; asm("mov.b64 %0, {%1,%2};" : "=l"(d) : "f"(lo), "f"(hi)); return d;
}
__device__ __forceinline__ void unpack2(uint64_t v, float& lo, float& hi) {
    asm("mov.b64 {%0,%1}, %2;" : "=f"(lo), "=f"(hi) : "l"(v));
}
__device__ __forceinline__ uint64_t fma2(uint64_t a, uint64_t b, uint64_t c) {
    uint64_t d; asm("fma.rn.f32x2 %0, %1, %2, %3;" : "=l"(d) : "l"(a), "l"(b), "l"(c)); return d;
}
__device__ __forceinline__ void lds_v2u64(uint64_t& a, uint64_t& b, uint32_t addr) {
    asm volatile("ld.shared.v2.u64 {%0,%1}, [%2];" : "=l"(a), "=l"(b) : "r"(addr));
}

// ---------------------------------------------------------------------------
// Proven GEMM body (R7, 70.4us): SA rows x 256 cols, K split in halves of 256
// across thread halves. Register ping-pong prefetch of W (2 blocks of 8 k).
// No barriers in the mainloop. Writes logits (+bias) to s_log.
// W reads via __ldg (ld.global.nc streaming path).
// ---------------------------------------------------------------------------
template <int SA>
__device__ __forceinline__ void gemm_body(
    const float* s_in_k, float* s_log,
    const float* __restrict__ wc,    // W + j + k0*HC
    int j, int half, float biasj)
{
    uint64_t acc[SA];
#pragma unroll
    for (int s = 0; s < SA; s++) acc[s] = 0ull;

    uint32_t sb = (uint32_t)__cvta_generic_to_shared(s_in_k);

    const int NBLK = (NH / 2) / 8;   // 32 blocks of 8 k
    float A[8], B[8];
#pragma unroll
    for (int i = 0; i < 8; i++) A[i] = __ldg(wc + (size_t)i * HC);
#pragma unroll
    for (int i = 0; i < 8; i++) B[i] = __ldg(wc + (size_t)(8 + i) * HC);

    for (int ib = 0; ib < NBLK; ib += 2) {
        {   // block ib (buffer A), prefetch A <- ib+2
            uint64_t wA = pack2(A[0], A[1]), wB = pack2(A[2], A[3]);
            uint64_t wC = pack2(A[4], A[5]), wD = pack2(A[6], A[7]);
            int ip = (ib + 2 < NBLK) ? (ib + 2) : ib;
            const float* wp = wc + (size_t)ip * 8 * HC;
#pragma unroll
            for (int i = 0; i < 8; i++) A[i] = __ldg(wp + (size_t)i * HC);

            uint32_t a = sb + ib * 32;
#pragma unroll
            for (int s = 0; s < SA; s++) {
                uint64_t v01, v23, v45, v67;
                lds_v2u64(v01, v23, a);
                lds_v2u64(v45, v67, a + 16);
                acc[s] = fma2(v01, wA, acc[s]);
                acc[s] = fma2(v23, wB, acc[s]);
                acc[s] = fma2(v45, wC, acc[s]);
                acc[s] = fma2(v67, wD, acc[s]);
                a += NH * 4;
            }
        }
        {   // block ib+1 (buffer B), prefetch B <- ib+3
            uint64_t wA = pack2(B[0], B[1]), wB = pack2(B[2], B[3]);
            uint64_t wC = pack2(B[4], B[5]), wD = pack2(B[6], B[7]);
            int ip = (ib + 3 < NBLK) ? (ib + 3) : (ib + 1);
            const float* wp = wc + (size_t)ip * 8 * HC;
#pragma unroll
            for (int i = 0; i < 8; i++) B[i] = __ldg(wp + (size_t)i * HC);

            uint32_t a = sb + (ib + 1) * 32;
#pragma unroll
            for (int s = 0; s < SA; s++) {
                uint64_t v01, v23, v45, v67;
                lds_v2u64(v01, v23, a);
                lds_v2u64(v45, v67, a + 16);
                acc[s] = fma2(v01, wA, acc[s]);
                acc[s] = fma2(v23, wB, acc[s]);
                acc[s] = fma2(v45, wC, acc[s]);
                acc[s] = fma2(v67, wD, acc[s]);
                a += NH * 4;
            }
        }
    }

    float r[SA];
#pragma unroll
    for (int s = 0; s < SA; s++) {
        float lo, hi; unpack2(acc[s], lo, hi);
        r[s] = lo + hi;
    }
    if (half == 1) {
#pragma unroll
        for (int s = 0; s < SA; s++) s_log[s * HC + j] = r[s];
    }
    __syncthreads();
    if (half == 0) {
#pragma unroll
        for (int s = 0; s < SA; s++) s_log[s * HC + j] = r[s] + s_log[s * HC + j] + biasj;
    }
    __syncthreads();
}

__device__ __forceinline__ void softmax_row(const float* row, int lane,
                                            float& m_out, float& sum_out)
{
    float m = -1e30f;
#pragma unroll
    for (int c = lane; c < HC; c += 32) m = fmaxf(m, row[c]);
#pragma unroll
    for (int o = 16; o > 0; o >>= 1) m = fmaxf(m, __shfl_xor_sync(0xffffffffu, m, o));
    float sum = 0.f;
#pragma unroll
    for (int c = lane; c < HC; c += 32) sum += __expf(row[c] - m);
#pragma unroll
    for (int o = 16; o > 0; o >>= 1) sum += __shfl_xor_sync(0xffffffffu, sum, o);
    m_out = m; sum_out = sum;
}

// ---------------------------------------------------------------------------
// Single-wave persistent kernel (R7 structure). Queue of 384 items:
//   item <  HC  : bottom parent p = item (512KB DRAM stream)
//   item >= HC  : top tile of 16 samples starting at (item-HC)*16
// All 296 CTAs pop until empty; last CTA to finish writes out and resets.
// ---------------------------------------------------------------------------
__global__ __launch_bounds__(512, 2) void fused_kernel(
    const float* __restrict__ inputs, const int* __restrict__ labels,
    const int* __restrict__ parent,
    const float* __restrict__ topW, const float* __restrict__ topB,
    const float* __restrict__ botW, const float* __restrict__ botB,
    float* __restrict__ out)
{
    extern __shared__ float sm[];
    float* s_in  = sm;
    float* s_log = sm + S_LOG;
    int* s_idx = (int*)(sm + S_IDX);
    int* s_cnt = (int*)(sm + S_CNT);
    int* s_pop = (int*)(sm + S_POP);

    int tid = threadIdx.x;
    int j = tid & (HC - 1);
    int half = tid >> 8;
    int k0 = half * (NH / 2);
    int wid = tid >> 5, lane = tid & 31;

    for (;;) {
        __syncthreads();                 // smem reuse across items
        if (tid == 0) *s_pop = atomicAdd(&g_queue, 1);
        __syncthreads();
        int item = *s_pop;
        if (item >= NQ) break;

        if (item >= HC) {
            // ----------------- TOP tile (16 samples) -----------------
            int b0 = (item - HC) * TOPT;
            const float4* gin = (const float4*)(inputs + (size_t)b0 * NH);
            float4* s4 = (float4*)s_in;
#pragma unroll
            for (int i = 0; i < TOPT * NH / 4 / 512; i++)
                s4[tid + i * 512] = gin[tid + i * 512];
            __syncthreads();

            gemm_body<TOPT>(s_in + k0, s_log, topW + j + (size_t)k0 * HC, j, half,
                            __ldg(topB + j));

            const float* row = s_log + wid * HC;
            float m, sum;
            softmax_row(row, lane, m, sum);
            if (lane == 0) {
                int b = b0 + wid;
                int p = parent[b];
                g_top_prob[b] = __expf(row[p] - m) / sum;
            }
        } else {
            // ----------------- BOTTOM parent -----------------
            int p = item;
            if (tid == 0) *s_cnt = 0;
            __syncthreads();
            for (int i = tid; i < BATCH; i += 512) {
                if (parent[i] == p) {
                    int q = atomicAdd(s_cnt, 1);
                    if (q < IDXCAP) s_idx[q] = i;
                }
            }
            __syncthreads();
            int n = min(*s_cnt, IDXCAP);
            if (n == 0) continue;

            const float* wc = botW + (size_t)p * NH * HC + j + (size_t)k0 * HC;
            float biasj = __ldg(botB + (size_t)p * HC + j);

            for (int c0 = 0; c0 < n; c0 += TILE) {
                int S = min(TILE, n - c0);
                __syncthreads();             // prev softmax done with s_log/s_in

                for (int i = tid; i < S * (NH / 4); i += 512) {
                    int s = i >> 7, q = i & 127;
                    int b = s_idx[c0 + s];
                    ((float4*)(s_in + s * NH))[q] = ((const float4*)(inputs + (size_t)b * NH))[q];
                }
                __syncthreads();

                switch ((S + 3) >> 2) {
                    case 1:  gemm_body<4>(s_in + k0, s_log, wc, j, half, biasj);  break;
                    case 2:  gemm_body<8>(s_in + k0, s_log, wc, j, half, biasj);  break;
                    case 3:  gemm_body<12>(s_in + k0, s_log, wc, j, half, biasj); break;
                    default: gemm_body<16>(s_in + k0, s_log, wc, j, half, biasj); break;
                }

                if (wid < S) {
                    const float* row = s_log + wid * HC;
                    float m, sum;
                    softmax_row(row, lane, m, sum);
                    if (lane == 0) {
                        int b = s_idx[c0 + wid];
                        int l = labels[b];
                        g_bot_prob[b] = __expf(row[l] - m) / sum;
                    }
                }
            }
        }
    }

    // ----------------- last-CTA finalize -----------------
    __syncthreads();
    __threadfence();
    if (tid == 0) *s_pop = atomicAdd(&g_done, 1);
    __syncthreads();
    if (*s_pop == GRID - 1) {
        __threadfence();
#pragma unroll
        for (int i = 0; i < BATCH / 512; i++) {
            int b = tid + i * 512;
            out[b] = g_top_prob[b] * g_bot_prob[b];
        }
        __threadfence();
        if (tid == 0) { g_done = 0; g_queue = 0; }
    }
}

// ---------------------------------------------------------------------------
extern "C" void kernel_launch(void* const* d_in, const int* in_sizes, int n_in,
                              void* d_out, int out_size) {
    const float* inputs = (const float*)d_in[0];
    const int*   labels = (const int*)d_in[1];
    const int*   parent = (const int*)d_in[2];
    const float* topW   = (const float*)d_in[3];
    const float* topB   = (const float*)d_in[4];
    const float* botW   = (const float*)d_in[5];
    const float* botB   = (const float*)d_in[6];
    float* out = (float*)d_out;

    cudaFuncSetAttribute(fused_kernel,
                         cudaFuncAttributeMaxDynamicSharedMemorySize, SMEM_BYTES);

    fused_kernel<<<GRID, 512, SMEM_BYTES>>>(inputs, labels, parent,
                                            topW, topB, botW, botB, out);
}

// round 13
// speedup vs baseline: 1.7083x; 1.1441x over previous
#include <cuda_runtime.h>
#include <cstdint>

#define BATCH 2048
#define NH    512
#define HC    256
#define ROWS  8            // rows per chunk / smem tile
#define NSL   4
#define KSL   (NH / NSL)   // 128 k per slice
#define TOPT  8
#define IDXCAP 128
#define GRID  296          // 148 SMs * 2 CTAs
#define NQ    (HC + BATCH / TOPT)   // 256 bottom + 256 top = 512 items

// smem byte offsets
#define OFF_IN   0                         // s_in: ROWS*NH f32 = 16384 B
#define OFF_LA   (ROWS * NH * 4)           // logA: ROWS*HC f32 = 8192 B
#define OFF_LB   (OFF_LA + ROWS * HC * 4)  // logB: 8192 B
#define OFF_IDX  (OFF_LB + ROWS * HC * 4)
#define OFF_CNT  (OFF_IDX + IDXCAP * 4)
#define OFF_POP  (OFF_CNT + 4)
#define SMEM_BYTES (OFF_POP + 12)          // ~33.3 KB -> 2 CTAs/SM easily

__device__ float g_top_prob[BATCH];
__device__ float g_bot_prob[BATCH];
__device__ int   g_queue;
__device__ int   g_done;

// ---------------- PTX helpers ----------------
__device__ __forceinline__ uint64_t pack2(float lo, float hi) {
    uint64_t d; asm("mov.b64 %0, {%1,%2};" : "=l"(d) : "f"(lo), "f"(hi)); return d;
}
__device__ __forceinline__ void unpack2(uint64_t v, float& lo, float& hi) {
    asm("mov.b64 {%0,%1}, %2;" : "=f"(lo), "=f"(hi) : "l"(v));
}
__device__ __forceinline__ uint64_t fma2(uint64_t a, uint64_t b, uint64_t c) {
    uint64_t d; asm("fma.rn.f32x2 %0, %1, %2, %3;" : "=l"(d) : "l"(a), "l"(b), "l"(c)); return d;
}
__device__ __forceinline__ uint64_t add2(uint64_t a, uint64_t b) {
    uint64_t d; asm("add.rn.f32x2 %0, %1, %2;" : "=l"(d) : "l"(a), "l"(b)); return d;
}
__device__ __forceinline__ void lds128(uint64_t& a, uint64_t& b, uint32_t addr) {
    asm volatile("ld.shared.v2.u64 {%0,%1}, [%2];" : "=l"(a), "=l"(b) : "r"(addr));
}
__device__ __forceinline__ uint64_t lds64(uint32_t addr) {
    uint64_t v; asm volatile("ld.shared.b64 %0, [%1];" : "=l"(v) : "r"(addr)); return v;
}
__device__ __forceinline__ void sts64(uint32_t addr, uint64_t v) {
    asm volatile("st.shared.b64 [%0], %1;" :: "r"(addr), "l"(v));
}

// ---------------------------------------------------------------------------
// 2-col GEMM slice: SA rows x cols {2g, 2g+1}, k in [q*KSL, (q+1)*KSL).
// x: plain (non-dup) s_in; broadcast LDS.128 = 4 k-values feeds 4 fma2 (2 cols).
// W: two scalar column streams (base wp, +1), 4+4 register ring per col,
//    prefetch distance 2 sub-blocks of 4k (R7/R11-proven pattern).
// acc: u64 over (k-even, k-odd) per col; horizontal add at end.
// Partials combined: q3->A, q2->B; sync; q1+=A, q0+=B+bias; sync.
// ---------------------------------------------------------------------------
template <int SA>
__device__ __forceinline__ void gemm2c(
    uint32_t xb,                   // smem addr of s_in[0][q*KSL]
    uint32_t la, uint32_t lb,      // smem addrs of logA/B [0][2g]
    const float* __restrict__ wp,  // W + (q*KSL)*HC + 2g  (col c0; c1 = +1)
    int q, uint64_t bias2)
{
    uint64_t acc0[SA], acc1[SA];
#pragma unroll
    for (int s = 0; s < SA; s++) { acc0[s] = 0ull; acc1[s] = 0ull; }

    const int NST = KSL / 4;       // 32 sub-blocks of 4 k
    float A0[4], A1[4], B0[4], B1[4];
#pragma unroll
    for (int i = 0; i < 4; i++) {
        A0[i] = wp[(size_t)i * HC];     A1[i] = wp[(size_t)i * HC + 1];
        B0[i] = wp[(size_t)(4 + i) * HC]; B1[i] = wp[(size_t)(4 + i) * HC + 1];
    }

    for (int st = 0; st < NST; st += 2) {
        {   // sub-block st (buffer A), prefetch A <- st+2
            uint64_t wA0 = pack2(A0[0], A0[1]), wB0 = pack2(A0[2], A0[3]);
            uint64_t wA1 = pack2(A1[0], A1[1]), wB1 = pack2(A1[2], A1[3]);
            int ip = (st + 2 < NST) ? (st + 2) : st;
            const float* wn = wp + (size_t)ip * 4 * HC;
#pragma unroll
            for (int i = 0; i < 4; i++) {
                A0[i] = wn[(size_t)i * HC]; A1[i] = wn[(size_t)i * HC + 1];
            }
            uint32_t xa = xb + (uint32_t)st * 16;
#pragma unroll
            for (int s = 0; s < SA; s++) {
                uint64_t x01, x23;
                lds128(x01, x23, xa);
                acc0[s] = fma2(x01, wA0, acc0[s]);
                acc0[s] = fma2(x23, wB0, acc0[s]);
                acc1[s] = fma2(x01, wA1, acc1[s]);
                acc1[s] = fma2(x23, wB1, acc1[s]);
                xa += NH * 4;
            }
        }
        {   // sub-block st+1 (buffer B), prefetch B <- st+3
            uint64_t wA0 = pack2(B0[0], B0[1]), wB0 = pack2(B0[2], B0[3]);
            uint64_t wA1 = pack2(B1[0], B1[1]), wB1 = pack2(B1[2], B1[3]);
            int ip = (st + 3 < NST) ? (st + 3) : (st + 1);
            const float* wn = wp + (size_t)ip * 4 * HC;
#pragma unroll
            for (int i = 0; i < 4; i++) {
                B0[i] = wn[(size_t)i * HC]; B1[i] = wn[(size_t)i * HC + 1];
            }
            uint32_t xa = xb + (uint32_t)(st + 1) * 16;
#pragma unroll
            for (int s = 0; s < SA; s++) {
                uint64_t x01, x23;
                lds128(x01, x23, xa);
                acc0[s] = fma2(x01, wA0, acc0[s]);
                acc0[s] = fma2(x23, wB0, acc0[s]);
                acc1[s] = fma2(x01, wA1, acc1[s]);
                acc1[s] = fma2(x23, wB1, acc1[s]);
                xa += NH * 4;
            }
        }
    }

    // horizontal add -> packed (c0,c1) per row
    uint64_t r[SA];
#pragma unroll
    for (int s = 0; s < SA; s++) {
        float l0, h0, l1, h1;
        unpack2(acc0[s], l0, h0);
        unpack2(acc1[s], l1, h1);
        r[s] = pack2(l0 + h0, l1 + h1);
    }

    // combine slices
    if (q == 3) {
#pragma unroll
        for (int s = 0; s < SA; s++) sts64(la + (uint32_t)s * (HC * 4), r[s]);
    } else if (q == 2) {
#pragma unroll
        for (int s = 0; s < SA; s++) sts64(lb + (uint32_t)s * (HC * 4), r[s]);
    }
    __syncthreads();
    if (q == 1) {
#pragma unroll
        for (int s = 0; s < SA; s++) {
            uint32_t a = la + (uint32_t)s * (HC * 4);
            sts64(a, add2(r[s], lds64(a)));
        }
    } else if (q == 0) {
#pragma unroll
        for (int s = 0; s < SA; s++) {
            uint32_t a = lb + (uint32_t)s * (HC * 4);
            sts64(a, add2(add2(r[s], bias2), lds64(a)));
        }
    }
    __syncthreads();
}

// softmax over A[c]+B[c]
__device__ __forceinline__ void softmax_row2(
    const float* A, const float* B, int lane, float& m_out, float& sum_out)
{
    float m = -1e30f;
#pragma unroll
    for (int cc = lane; cc < HC; cc += 32) m = fmaxf(m, A[cc] + B[cc]);
#pragma unroll
    for (int o = 16; o > 0; o >>= 1) m = fmaxf(m, __shfl_xor_sync(0xffffffffu, m, o));
    float sum = 0.f;
#pragma unroll
    for (int cc = lane; cc < HC; cc += 32) sum += __expf(A[cc] + B[cc] - m);
#pragma unroll
    for (int o = 16; o > 0; o >>= 1) sum += __shfl_xor_sync(0xffffffffu, sum, o);
    m_out = m; sum_out = sum;
}

// ---------------------------------------------------------------------------
__global__ __launch_bounds__(512, 2) void fused_kernel(
    const float* __restrict__ inputs, const int* __restrict__ labels,
    const int* __restrict__ parent,
    const float* __restrict__ topW, const float* __restrict__ topB,
    const float* __restrict__ botW, const float* __restrict__ botB,
    float* __restrict__ out)
{
    extern __shared__ char sm[];
    uint32_t sb = (uint32_t)__cvta_generic_to_shared(sm);
    float* s_in   = (float*)(sm + OFF_IN);
    float* s_logA = (float*)(sm + OFF_LA);
    float* s_logB = (float*)(sm + OFF_LB);
    int* s_idx = (int*)(sm + OFF_IDX);
    int* s_cnt = (int*)(sm + OFF_CNT);
    int* s_pop = (int*)(sm + OFF_POP);

    int tid = threadIdx.x;
    int q = tid >> 7;            // k-slice 0..3
    int g = tid & 127;           // column pair {2g, 2g+1}
    int wid = tid >> 5, lane = tid & 31;

    uint32_t xb = sb + OFF_IN + (uint32_t)(q * KSL) * 4;
    uint32_t la = sb + OFF_LA + (uint32_t)g * 8;
    uint32_t lb = sb + OFF_LB + (uint32_t)g * 8;

    for (;;) {
        __syncthreads();
        if (tid == 0) *s_pop = atomicAdd(&g_queue, 1);
        __syncthreads();
        int item = *s_pop;
        if (item >= NQ) break;

        if (item >= HC) {
            // ----------------- TOP tile (8 samples) -----------------
            int b0 = (item - HC) * TOPT;
            const float4* gin = (const float4*)(inputs + (size_t)b0 * NH);
            float4* s4 = (float4*)s_in;
#pragma unroll
            for (int i = 0; i < TOPT * NH / 4 / 512; i++)
                s4[tid + i * 512] = gin[tid + i * 512];
            __syncthreads();

            float2 bv = *(const float2*)(topB + 2 * g);
            gemm2c<TOPT>(xb, la, lb, topW + (size_t)(q * KSL) * HC + 2 * g, q,
                         pack2(bv.x, bv.y));

            if (wid < TOPT) {
                const float* A = s_logA + wid * HC;
                const float* B = s_logB + wid * HC;
                float m, sum;
                softmax_row2(A, B, lane, m, sum);
                if (lane == 0) {
                    int b = b0 + wid;
                    int p = parent[b];
                    g_top_prob[b] = __expf(A[p] + B[p] - m) / sum;
                }
            }
        } else {
            // ----------------- BOTTOM parent -----------------
            int p = item;
            if (tid == 0) *s_cnt = 0;
            __syncthreads();
            for (int i = tid; i < BATCH; i += 512) {
                if (parent[i] == p) {
                    int qq = atomicAdd(s_cnt, 1);
                    if (qq < IDXCAP) s_idx[qq] = i;
                }
            }
            __syncthreads();
            int n = min(*s_cnt, IDXCAP);
            if (n == 0) continue;

            const float* wp = botW + (size_t)p * NH * HC + (size_t)(q * KSL) * HC + 2 * g;
            float2 bv = *(const float2*)(botB + (size_t)p * HC + 2 * g);
            uint64_t bias2 = pack2(bv.x, bv.y);

            for (int c0 = 0; c0 < n; c0 += ROWS) {
                int S = min(ROWS, n - c0);
                __syncthreads();             // prev softmax done with logs/s_in

                for (int i = tid; i < S * (NH / 4); i += 512) {
                    int s = i >> 7, qq = i & 127;
                    int b = s_idx[c0 + s];
                    ((float4*)(s_in + s * NH))[qq] = ((const float4*)(inputs + (size_t)b * NH))[qq];
                }
                __syncthreads();

                if (S <= 4) gemm2c<4>(xb, la, lb, wp, q, bias2);
                else        gemm2c<8>(xb, la, lb, wp, q, bias2);

                if (wid < S) {
                    const float* A = s_logA + wid * HC;
                    const float* B = s_logB + wid * HC;
                    float m, sum;
                    softmax_row2(A, B, lane, m, sum);
                    if (lane == 0) {
                        int b = s_idx[c0 + wid];
                        int l = labels[b];
                        g_bot_prob[b] = __expf(A[l] + B[l] - m) / sum;
                    }
                }
            }
        }
    }

    // ----------------- last-CTA finalize -----------------
    __syncthreads();
    __threadfence();
    if (tid == 0) *s_pop = atomicAdd(&g_done, 1);
    __syncthreads();
    if (*s_pop == GRID - 1) {
        __threadfence();
#pragma unroll
        for (int i = 0; i < BATCH / 512; i++) {
            int b = tid + i * 512;
            out[b] = g_top_prob[b] * g_bot_prob[b];
        }
        __threadfence();
        if (tid == 0) { g_done = 0; g_queue = 0; }
    }
}

// ---------------------------------------------------------------------------
extern "C" void kernel_launch(void* const* d_in, const int* in_sizes, int n_in,
                              void* d_out, int out_size) {
    const float* inputs = (const float*)d_in[0];
    const int*   labels = (const int*)d_in[1];
    const int*   parent = (const int*)d_in[2];
    const float* topW   = (const float*)d_in[3];
    const float* topB   = (const float*)d_in[4];
    const float* botW   = (const float*)d_in[5];
    const float* botB   = (const float*)d_in[6];
    float* out = (float*)d_out;

    cudaFuncSetAttribute(fused_kernel,
                         cudaFuncAttributeMaxDynamicSharedMemorySize, SMEM_BYTES);

    fused_kernel<<<GRID, 512, SMEM_BYTES>>>(inputs, labels, parent,
                                            topW, topB, botW, botB, out);
}

// round 15
// speedup vs baseline: 1.9835x; 1.1611x over previous
#include <cuda_runtime.h>
#include <cstdint>

#define BATCH 2048
#define NH    512
#define HC    256
#define ROWS  16            // rows per chunk (one m16 tile)
#define IDXCAP 128
#define GRID  296
#define NTOPI (BATCH / ROWS)       // 128 top items
#define NQ    (HC + NTOPI)         // 384 items
#define NTHR  256
#define XPITCH 1040         // 512 bf16 + 16B pad -> conflict-free ldmatrix

// smem byte offsets
#define OFF_XH  0                   // 16 * 1040
#define OFF_XL  16640
#define OFF_LG  33280               // 16*256*4
#define OFF_IDX 49664
#define OFF_CNT (OFF_IDX + IDXCAP * 4)
#define OFF_POP (OFF_CNT + 4)
#define SMEM_BYTES (OFF_POP + 12)   // ~50.2 KB -> 2 CTAs/SM

__device__ float g_top_prob[BATCH];
__device__ float g_bot_prob[BATCH];
__device__ int   g_queue;
__device__ int   g_done;

// ---------------- PTX helpers (all baseline ISA, no 'a' features) ----------
__device__ __forceinline__ uint32_t cvt2bf(float hi, float lo) {
    uint32_t r; asm("cvt.rn.bf16x2.f32 %0, %1, %2;" : "=r"(r) : "f"(hi), "f"(lo));
    return r;
}
__device__ __forceinline__ void sts64(uint32_t a, uint64_t v) {
    asm volatile("st.shared.b64 [%0], %1;" :: "r"(a), "l"(v));
}
__device__ __forceinline__ void ldmx4(uint32_t* r, uint32_t addr) {
    asm volatile("ldmatrix.sync.aligned.m8n8.x4.shared.b16 {%0,%1,%2,%3}, [%4];"
        : "=r"(r[0]), "=r"(r[1]), "=r"(r[2]), "=r"(r[3]) : "r"(addr));
}
__device__ __forceinline__ void mma16816(float* d, const uint32_t* a,
                                         const uint32_t* b) {
    asm volatile(
        "mma.sync.aligned.m16n8k16.row.col.f32.bf16.bf16.f32 "
        "{%0,%1,%2,%3}, {%4,%5,%6,%7}, {%8,%9}, {%0,%1,%2,%3};"
        : "+f"(d[0]), "+f"(d[1]), "+f"(d[2]), "+f"(d[3])
        : "r"(a[0]), "r"(a[1]), "r"(a[2]), "r"(a[3]), "r"(b[0]), "r"(b[1]));
}
// split (f0, f1) -> bf16x2 hi-part h and residual-lo l  (lo half = f0)
__device__ __forceinline__ void bsplit(float f0, float f1, uint32_t& h, uint32_t& l) {
    h = cvt2bf(f1, f0);
    float r0 = __uint_as_float(h << 16);
    float r1 = __uint_as_float(h & 0xffff0000u);
    l = cvt2bf(f1 - r1, f0 - r0);
}

__device__ __forceinline__ void softmax_row(const float* row, int lane,
                                            float& m_out, float& sum_out)
{
    float m = -1e30f;
#pragma unroll
    for (int c = lane; c < HC; c += 32) m = fmaxf(m, row[c]);
#pragma unroll
    for (int o = 16; o > 0; o >>= 1) m = fmaxf(m, __shfl_xor_sync(0xffffffffu, m, o));
    float sum = 0.f;
#pragma unroll
    for (int c = lane; c < HC; c += 32) sum += __expf(row[c] - m);
#pragma unroll
    for (int o = 16; o > 0; o >>= 1) sum += __shfl_xor_sync(0xffffffffu, sum, o);
    m_out = m; sum_out = sum;
}

// ---------------------------------------------------------------------------
// Persistent HMMA kernel. 256 thr (8 warps), 2 CTAs/SM, queue of 384 items:
//   item < 256  : bottom parent (chunks of 16 rows; W[p] streamed from DRAM)
//   item >= 256 : top tile of 16 samples (W_top L2-resident)
// Per chunk: logits[16,256] = X[16,512] @ W[512,256] via m16n8k16 bf16 MMA,
// 3-term hi/lo split for fp32-grade accuracy. Warp w owns cols [32w, 32w+32).
// ---------------------------------------------------------------------------
__global__ __launch_bounds__(NTHR, 2) void fused_kernel(
    const float* __restrict__ inputs, const int* __restrict__ labels,
    const int* __restrict__ parent,
    const float* __restrict__ topW, const float* __restrict__ topB,
    const float* __restrict__ botW, const float* __restrict__ botB,
    float* __restrict__ out)
{
    extern __shared__ char smc[];
    uint32_t sb = (uint32_t)__cvta_generic_to_shared(smc);
    float* lg   = (float*)(smc + OFF_LG);
    int* srows  = (int*)(smc + OFF_IDX);
    int* s_cnt  = (int*)(smc + OFF_CNT);
    int* s_pop  = (int*)(smc + OFF_POP);

    int tid = threadIdx.x;
    int wid = tid >> 5, lane = tid & 31;
    int lg4 = lane >> 2, l4 = lane & 3;
    int nb = wid * 32;

    // ldmatrix per-lane base address (row/col mapping for m16k16 A fragments)
    uint32_t lmoff = (uint32_t)((lane & 7) + ((lane >> 3) & 1) * 8) * XPITCH
                   + (uint32_t)((lane >> 4) * 8) * 2;
    uint32_t xh_lm = sb + OFF_XH + lmoff;
    uint32_t xl_lm = sb + OFF_XL + lmoff;

    for (;;) {
        __syncthreads();
        if (tid == 0) *s_pop = atomicAdd(&g_queue, 1);
        __syncthreads();
        int item = *s_pop;
        if (item >= NQ) break;

        bool isTop = (item >= HC);
        const float* Wp;
        const float* biasp;
        int n;
        if (isTop) {
            Wp = topW; biasp = topB;
            int b0 = (item - HC) * ROWS;
            if (tid < ROWS) srows[tid] = b0 + tid;
            n = ROWS;
            __syncthreads();
        } else {
            int p = item;
            Wp = botW + (size_t)p * NH * HC;
            biasp = botB + (size_t)p * HC;
            if (tid == 0) *s_cnt = 0;
            __syncthreads();
            for (int i = tid; i < BATCH; i += NTHR) {
                if (parent[i] == p) {
                    int q = atomicAdd(s_cnt, 1);
                    if (q < IDXCAP) srows[q] = i;
                }
            }
            __syncthreads();
            n = min(*s_cnt, IDXCAP);
            if (n == 0) continue;
        }

        for (int c0 = 0; c0 < n; c0 += ROWS) {
            int S = min(ROWS, n - c0);

            // ---- X -> smem bf16 hi/lo (rows >= S zero-filled) ----
            for (int idx = tid; idx < ROWS * 128; idx += NTHR) {
                int s = idx >> 7, kq = idx & 127;
                uint64_t hv = 0, lv = 0;
                if (s < S) {
                    int row = srows[c0 + s];
                    float4 v = __ldg((const float4*)(inputs + (size_t)row * NH) + kq);
                    uint32_t h01 = cvt2bf(v.y, v.x);
                    uint32_t h23 = cvt2bf(v.w, v.z);
                    float rx = __uint_as_float(h01 << 16);
                    float ry = __uint_as_float(h01 & 0xffff0000u);
                    float rz = __uint_as_float(h23 << 16);
                    float rw = __uint_as_float(h23 & 0xffff0000u);
                    uint32_t l01 = cvt2bf(v.y - ry, v.x - rx);
                    uint32_t l23 = cvt2bf(v.w - rw, v.z - rz);
                    hv = (uint64_t)h01 | ((uint64_t)h23 << 32);
                    lv = (uint64_t)l01 | ((uint64_t)l23 << 32);
                }
                uint32_t off = (uint32_t)s * XPITCH + (uint32_t)kq * 8;
                sts64(sb + OFF_XH + off, hv);
                sts64(sb + OFF_XL + off, lv);
            }
            __syncthreads();

            // ---- k-loop: 32 steps of k16, per-warp independent ----
            float acc[4][4];
#pragma unroll
            for (int nt = 0; nt < 4; nt++)
#pragma unroll
                for (int e = 0; e < 4; e++) acc[nt][e] = 0.f;

            // B element addresses: rows 2*l4 +{0,1,8,9}, col nb + lg4 + nt*8
            const float* wb = Wp + (size_t)(2 * l4) * HC + nb + lg4;

            float fr[4][4];
#pragma unroll
            for (int nt = 0; nt < 4; nt++) {
                const float* p = wb + nt * 8;
                fr[nt][0] = __ldg(p);
                fr[nt][1] = __ldg(p + HC);
                fr[nt][2] = __ldg(p + 8 * HC);
                fr[nt][3] = __ldg(p + 9 * HC);
            }

#pragma unroll 2
            for (int ks = 0; ks < 32; ks++) {
                // prefetch next k-step's W elements
                float fn[4][4];
                int kn = (ks + 1 < 32) ? (ks + 1) : ks;
                const float* wnx = wb + (size_t)(kn * 16) * HC;
#pragma unroll
                for (int nt = 0; nt < 4; nt++) {
                    const float* p = wnx + nt * 8;
                    fn[nt][0] = __ldg(p);
                    fn[nt][1] = __ldg(p + HC);
                    fn[nt][2] = __ldg(p + 8 * HC);
                    fn[nt][3] = __ldg(p + 9 * HC);
                }

                uint32_t Ah[4], Al[4];
                ldmx4(Ah, xh_lm + (uint32_t)ks * 32);
                ldmx4(Al, xl_lm + (uint32_t)ks * 32);

#pragma unroll
                for (int nt = 0; nt < 4; nt++) {
                    uint32_t bh[2], bl[2];
                    bsplit(fr[nt][0], fr[nt][1], bh[0], bl[0]);
                    bsplit(fr[nt][2], fr[nt][3], bh[1], bl[1]);
                    mma16816(acc[nt], Ah, bh);   // Wh * Xh
                    mma16816(acc[nt], Al, bh);   // Wh * Xl
                    mma16816(acc[nt], Ah, bl);   // Wl * Xh
                }
#pragma unroll
                for (int nt = 0; nt < 4; nt++)
#pragma unroll
                    for (int e = 0; e < 4; e++) fr[nt][e] = fn[nt][e];
            }

            // ---- epilogue: acc + bias -> logits smem ----
#pragma unroll
            for (int nt = 0; nt < 4; nt++) {
                int c = nb + nt * 8 + 2 * l4;
                float2 bv = *(const float2*)(biasp + c);
                int g = lg4;
                lg[g * HC + c]           = acc[nt][0] + bv.x;
                lg[g * HC + c + 1]       = acc[nt][1] + bv.y;
                lg[(g + 8) * HC + c]     = acc[nt][2] + bv.x;
                lg[(g + 8) * HC + c + 1] = acc[nt][3] + bv.y;
            }
            __syncthreads();

            // ---- softmax + output (2 rows per warp) ----
            for (int r = wid; r < S; r += 8) {
                const float* row = lg + r * HC;
                float m, sum;
                softmax_row(row, lane, m, sum);
                if (lane == 0) {
                    int b = srows[c0 + r];
                    if (isTop) {
                        int pp = parent[b];
                        g_top_prob[b] = __expf(row[pp] - m) / sum;
                    } else {
                        int l = labels[b];
                        g_bot_prob[b] = __expf(row[l] - m) / sum;
                    }
                }
            }
            __syncthreads();   // smem reuse next chunk
        }
    }

    // ---- last-CTA finalize ----
    __syncthreads();
    __threadfence();
    if (tid == 0) *s_pop = atomicAdd(&g_done, 1);
    __syncthreads();
    if (*s_pop == GRID - 1) {
        __threadfence();
#pragma unroll
        for (int i = 0; i < BATCH / NTHR; i++) {
            int b = tid + i * NTHR;
            out[b] = g_top_prob[b] * g_bot_prob[b];
        }
        __threadfence();
        if (tid == 0) { g_done = 0; g_queue = 0; }
    }
}

// ---------------------------------------------------------------------------
extern "C" void kernel_launch(void* const* d_in, const int* in_sizes, int n_in,
                              void* d_out, int out_size) {
    const float* inputs = (const float*)d_in[0];
    const int*   labels = (const int*)d_in[1];
    const int*   parent = (const int*)d_in[2];
    const float* topW   = (const float*)d_in[3];
    const float* topB   = (const float*)d_in[4];
    const float* botW   = (const float*)d_in[5];
    const float* botB   = (const float*)d_in[6];
    float* out = (float*)d_out;

    cudaFuncSetAttribute(fused_kernel,
                         cudaFuncAttributeMaxDynamicSharedMemorySize, SMEM_BYTES);

    fused_kernel<<<GRID, NTHR, SMEM_BYTES>>>(inputs, labels, parent,
                                             topW, topB, botW, botB, out);
}